// round 6
// baseline (speedup 1.0000x reference)
#include <cuda_runtime.h>

// PartialSum: out[b, p] = sum over 64 contiguous floats of x[b, p*64 : (p+1)*64]
// x: [2048, 65536] f32  -> out: [2048, 1024] f32 (2,097,152 partitions)
//
// R4 structure (coalesced, MLP=4, 16 lanes/partition, 4 shuffle trees) with
// streaming cache policy: __ldcs (evict-first L1+L2) for the read-once input,
// __stcs for the write-once output. Goal: cut L2 replacement overhead and
// push HBM efficiency from 85% toward ~89%.

__global__ void __launch_bounds__(256) partial_sum_kernel(
    const float4* __restrict__ x4, float* __restrict__ out)
{
    int t = threadIdx.x;
    int base = blockIdx.x * 1024 + t;              // float4 index of load 0

    // 4 independent, individually warp-coalesced streaming loads.
    float4 a = __ldcs(&x4[base]);
    float4 b = __ldcs(&x4[base + 256]);
    float4 c = __ldcs(&x4[base + 512]);
    float4 d = __ldcs(&x4[base + 768]);

    float sa = (a.x + a.y) + (a.z + a.w);
    float sb = (b.x + b.y) + (b.z + b.w);
    float sc = (c.x + c.y) + (c.z + c.w);
    float sd = (d.x + d.y) + (d.z + d.w);

    // 4 independent 16-lane reduction trees (interleaved for ILP).
    #pragma unroll
    for (int off = 8; off > 0; off >>= 1) {
        sa += __shfl_down_sync(0xffffffffu, sa, off, 16);
        sb += __shfl_down_sync(0xffffffffu, sb, off, 16);
        sc += __shfl_down_sync(0xffffffffu, sc, off, 16);
        sd += __shfl_down_sync(0xffffffffu, sd, off, 16);
    }

    if ((t & 15) == 0) {
        int p = blockIdx.x * 64 + (t >> 4);        // partition of load 0
        __stcs(&out[p],      sa);
        __stcs(&out[p + 16], sb);
        __stcs(&out[p + 32], sc);
        __stcs(&out[p + 48], sd);
    }
}

extern "C" void kernel_launch(void* const* d_in, const int* in_sizes, int n_in,
                              void* d_out, int out_size)
{
    const float4* x4 = (const float4*)d_in[0];
    float* out = (float*)d_out;

    int blocks = out_size / 64;                    // 2,097,152 / 64 = 32768
    partial_sum_kernel<<<blocks, 256>>>(x4, out);
}